// round 2
// baseline (speedup 1.0000x reference)
#include <cuda_runtime.h>

// Problem dims
#define Bb 8
#define Kk 1024
#define Ll 1024
#define Dd 1024
#define Oo 6
#define Ee 128
#define EPSf 1e-8f

// Scratch (device globals: allocation-free)
__device__ float g_priors[(size_t)Oo * Bb * Kk * Ee];  // [o][b][k][e]  (25 MB)
__device__ float g_v[Bb * Oo * Ee];                    // squashed v per (b,o)
__device__ float g_logits[Bb * Kk * Oo];
__device__ float g_probs[Bb * Kk * Oo];                // [b][k][o]

// ---------------------------------------------------------------------------
// Kernel 1: priors GEMM.  For each o: C[8192 x 128] = U[8192 x 1024] * W_o[1024 x 128]
// Tile: BM=64, BN=128 (full E), BK=16. 256 threads, 8x4 micro-tile per thread.
// ---------------------------------------------------------------------------
__global__ void __launch_bounds__(256) gemm_priors(const float* __restrict__ U,
                                                   const float* __restrict__ W) {
    const int o    = blockIdx.y;
    const int row0 = blockIdx.x * 64;

    __shared__ float As[16][64];   // [k][m] transposed
    __shared__ float Bs[16][128];  // [k][e]

    const int tid = threadIdx.x;
    const int tm  = (tid >> 5) * 8;   // 0..56 (warp id * 8 rows)
    const int tn  = (tid & 31) * 4;   // 0..124

    // A-tile load mapping: 64x16 floats, 4 per thread (float4 along k)
    const int am = tid >> 2;          // 0..63
    const int ak = (tid & 3) * 4;     // 0,4,8,12
    // B-tile load mapping: 16x128, 8 per thread (2x float4)
    const int bk = tid >> 5;          // 0..7
    const int be = (tid & 31) * 4;    // 0..124

    const float* Wo = W + (size_t)o * Dd * Ee;

    float acc[8][4];
#pragma unroll
    for (int j = 0; j < 8; j++)
#pragma unroll
        for (int i = 0; i < 4; i++) acc[j][i] = 0.f;

    for (int k0 = 0; k0 < Dd; k0 += 16) {
        float4 a = *reinterpret_cast<const float4*>(&U[(size_t)(row0 + am) * Dd + k0 + ak]);
        As[ak + 0][am] = a.x;
        As[ak + 1][am] = a.y;
        As[ak + 2][am] = a.z;
        As[ak + 3][am] = a.w;
        float4 b0 = *reinterpret_cast<const float4*>(&Wo[(size_t)(k0 + bk) * Ee + be]);
        float4 b1 = *reinterpret_cast<const float4*>(&Wo[(size_t)(k0 + bk + 8) * Ee + be]);
        *reinterpret_cast<float4*>(&Bs[bk][be])     = b0;
        *reinterpret_cast<float4*>(&Bs[bk + 8][be]) = b1;
        __syncthreads();

#pragma unroll
        for (int kk = 0; kk < 16; kk++) {
            float4 bf = *reinterpret_cast<const float4*>(&Bs[kk][tn]);
#pragma unroll
            for (int j = 0; j < 8; j++) {
                float av = As[kk][tm + j];
                acc[j][0] += av * bf.x;
                acc[j][1] += av * bf.y;
                acc[j][2] += av * bf.z;
                acc[j][3] += av * bf.w;
            }
        }
        __syncthreads();
    }

    float* outp = g_priors + ((size_t)o * (Bb * Kk) + row0) * Ee;
#pragma unroll
    for (int j = 0; j < 8; j++) {
        float4 r = make_float4(acc[j][0], acc[j][1], acc[j][2], acc[j][3]);
        *reinterpret_cast<float4*>(&outp[(size_t)(tm + j) * Ee + tn]) = r;
    }
}

// ---------------------------------------------------------------------------
// Kernel 2: s[b,o,e] = sum_k probs[b,k,o] * priors[o,b,k,e]; v = squash(s).
// One block per (b,o): 48 blocks, 512 threads (128 e-lanes x 4 k-slices).
// ---------------------------------------------------------------------------
__global__ void __launch_bounds__(512) s_squash(int uniform) {
    const int bo = blockIdx.x;  // 0..47
    const int b  = bo / Oo;
    const int o  = bo % Oo;
    const int e     = threadIdx.x & 127;
    const int slice = threadIdx.x >> 7;  // 0..3

    const float* P = g_priors + ((size_t)(o * Bb + b) * Kk) * Ee;

    float s = 0.f;
    const int kbeg = slice * (Kk / 4);
    if (uniform) {
#pragma unroll 8
        for (int k = kbeg; k < kbeg + (Kk / 4); k++)
            s += P[(size_t)k * Ee + e];
        s *= (1.f / 6.f);
    } else {
        const float* pr = g_probs + (size_t)b * Kk * Oo + o;
#pragma unroll 8
        for (int k = kbeg; k < kbeg + (Kk / 4); k++)
            s += pr[(size_t)k * Oo] * P[(size_t)k * Ee + e];
    }

    __shared__ float red[4][128];
    red[slice][e] = s;
    __syncthreads();

    __shared__ float sv[128];
    __shared__ float warpsum[4];
    if (slice == 0) {
        float total = red[0][e] + red[1][e] + red[2][e] + red[3][e];
        sv[e] = total;
        float x2 = total * total;
#pragma unroll
        for (int off = 16; off > 0; off >>= 1)
            x2 += __shfl_down_sync(0xffffffffu, x2, off);
        if ((e & 31) == 0) warpsum[e >> 5] = x2;
    }
    __syncthreads();
    if (slice == 0) {
        float sq   = warpsum[0] + warpsum[1] + warpsum[2] + warpsum[3];
        float coef = sq / ((1.f + sq) * (sqrtf(sq) + EPSf));
        g_v[(size_t)(b * Oo + o) * Ee + e] = sv[e] * coef;
    }
}

// ---------------------------------------------------------------------------
// Kernel 3: logits[b,k,o] (+)= sum_e priors[o,b,k,e]*v[b,o,e]; probs = softmax_o
// (masked -> uniform 1/6). One block per (b,k): 8192 blocks, 6 warps (one per o).
// mask is int32 (numpy bool promoted by the harness).
// ---------------------------------------------------------------------------
__global__ void __launch_bounds__(192) logits_probs(const int* __restrict__ mask,
                                                    int first) {
    const int bkidx = blockIdx.x;       // b*K + k
    const int b     = bkidx >> 10;
    const int o     = threadIdx.x >> 5; // warp id = o
    const int lane  = threadIdx.x & 31;

    const float* P = g_priors + ((size_t)(o * Bb + b) * Kk + (bkidx & (Kk - 1))) * Ee;
    const float* v = g_v + (size_t)(b * Oo + o) * Ee;

    float d = 0.f;
#pragma unroll
    for (int j = 0; j < 4; j++) {
        int e = lane + 32 * j;
        d += P[e] * v[e];
    }
#pragma unroll
    for (int off = 16; off > 0; off >>= 1)
        d += __shfl_down_sync(0xffffffffu, d, off);

    __shared__ float lg[Oo];
    if (lane == 0) {
        float lgv = first ? d : (g_logits[(size_t)bkidx * Oo + o] + d);
        g_logits[(size_t)bkidx * Oo + o] = lgv;
        lg[o] = lgv;
    }
    __syncthreads();

    if (threadIdx.x == 0) {
        float pr[Oo];
        if (mask[bkidx] != 0) {
#pragma unroll
            for (int i = 0; i < Oo; i++) pr[i] = 1.f / 6.f;
        } else {
            float mx = lg[0];
#pragma unroll
            for (int i = 1; i < Oo; i++) mx = fmaxf(mx, lg[i]);
            float sum = 0.f;
#pragma unroll
            for (int i = 0; i < Oo; i++) { pr[i] = expf(lg[i] - mx); sum += pr[i]; }
            float inv = 1.f / sum;
#pragma unroll
            for (int i = 0; i < Oo; i++) pr[i] *= inv;
        }
#pragma unroll
        for (int i = 0; i < Oo; i++) g_probs[(size_t)bkidx * Oo + i] = pr[i];
    }
}

// ---------------------------------------------------------------------------
// Kernel 4: broadcast v[b,o,e] -> out_v[b,l,o,e]  (float4, 25 MB writes)
// ---------------------------------------------------------------------------
__global__ void bcast_v(float4* __restrict__ out) {
    const int total4 = Bb * Ll * Oo * Ee / 4;  // 1,572,864
    int idx = blockIdx.x * blockDim.x + threadIdx.x;
    if (idx >= total4) return;
    int e4 = idx & 31;            // Ee/4 = 32
    int o  = (idx >> 5) % Oo;
    int bl = idx / (32 * Oo);
    int b  = bl >> 10;            // L = 1024
    out[idx] = *reinterpret_cast<const float4*>(&g_v[(size_t)(b * Oo + o) * Ee + e4 * 4]);
}

// ---------------------------------------------------------------------------
// Kernel 5: broadcast probs[b,k,o] -> out_p[b,l,k,o]  (201 MB writes)
// One block per (b,l), copies the 6144-float (b,·) slice.
// ---------------------------------------------------------------------------
__global__ void __launch_bounds__(256) bcast_probs(float* __restrict__ out) {
    const int bl = blockIdx.x;  // b*L + l
    const int b  = bl >> 10;
    const float4* src = reinterpret_cast<const float4*>(g_probs + (size_t)b * (Kk * Oo));
    float4* dst       = reinterpret_cast<float4*>(out + (size_t)bl * (Kk * Oo));
#pragma unroll
    for (int i = threadIdx.x; i < (Kk * Oo / 4); i += 256)
        dst[i] = src[i];
}

// ---------------------------------------------------------------------------
extern "C" void kernel_launch(void* const* d_in, const int* in_sizes, int n_in,
                              void* d_out, int out_size) {
    const float* U = (const float*)d_in[0];               // inputs_u (B,K,D)
    // d_in[1] = context_sequence : provably unused by the reference math
    const float* W = (const float*)d_in[2];               // route_weights (O,D,E)
    const int* mask = (const int*)d_in[3];                // inputs_mask (B,K), bool->int32

    float* out_v = (float*)d_out;                                   // (B,L,O,E)
    float* out_p = (float*)d_out + (size_t)Bb * Ll * Oo * Ee;       // (B,L,K,O)

    // 1. priors = einsum('bkd,ode->bkoe') stored as [o][b][k][e]
    gemm_priors<<<dim3((Bb * Kk) / 64, Oo), 256>>>(U, W);

    // 2. Routing iterations (L-independent; see analysis)
    s_squash<<<Bb * Oo, 512>>>(1);          // iter 0: uniform probs -> v0
    logits_probs<<<Bb * Kk, 192>>>(mask, 1);  // logits1, probs1
    s_squash<<<Bb * Oo, 512>>>(0);          // iter 1: v1
    logits_probs<<<Bb * Kk, 192>>>(mask, 0);  // logits2, probs2
    s_squash<<<Bb * Oo, 512>>>(0);          // iter 2: v2 (final)

    // 3. Broadcast over L to outputs
    bcast_v<<<(Bb * Ll * Oo * Ee / 4 + 255) / 256, 256>>>((float4*)out_v);
    bcast_probs<<<Bb * Ll, 256>>>(out_p);
}

// round 4
// speedup vs baseline: 2.0886x; 2.0886x over previous
#include <cuda_runtime.h>

// Problem dims
#define Bb 8
#define Kk 1024
#define Ll 1024
#define Dd 1024
#define Oo 6
#define Ee 128
#define EPSf 1e-8f

// Scratch (device globals: allocation-free)
__device__ float g_priors[(size_t)Oo * Bb * Kk * Ee];  // [o][b][k][e]  (25 MB)
__device__ float g_v[Bb * Oo * Ee];                    // squashed v per (b,o)
__device__ float g_logits[Bb * Kk * Oo];
__device__ float g_probs[Bb * Kk * Oo];                // [b][k][o]
__device__ float g_spart[8 * 48 * Ee];                 // k-sliced partial sums

__device__ __forceinline__ unsigned f2tf32(float f) {
    unsigned r;
    asm("cvt.rna.tf32.f32 %0, %1;" : "=r"(r) : "f"(f));
    return r;
}

__device__ __forceinline__ void mma_tf32(float* c, const unsigned* a, unsigned b0, unsigned b1) {
    asm volatile(
        "mma.sync.aligned.m16n8k8.row.col.f32.tf32.tf32.f32 "
        "{%0,%1,%2,%3}, {%4,%5,%6,%7}, {%8,%9}, {%0,%1,%2,%3};\n"
        : "+f"(c[0]), "+f"(c[1]), "+f"(c[2]), "+f"(c[3])
        : "r"(a[0]), "r"(a[1]), "r"(a[2]), "r"(a[3]), "r"(b0), "r"(b1));
}

// ---------------------------------------------------------------------------
// Kernel 1: priors GEMM via tf32 tensor-core mma.
// For each o: C[8192 x 128] = U[8192 x 1024] * W_o[1024 x 128]
// Block tile 128x128xK32, 256 threads = 8 warps (4 m x 2 n), warp tile 32x64.
// ---------------------------------------------------------------------------
#define ASTRIDE 36   // 32 + 4 pad  -> conflict-free frag loads
#define BSTRIDE 136  // 128 + 8 pad -> conflict-free frag loads

__global__ void __launch_bounds__(256) gemm_priors(const float* __restrict__ U,
                                                   const float* __restrict__ W) {
    const int o    = blockIdx.y;
    const int row0 = blockIdx.x * 128;

    __shared__ unsigned As[128 * ASTRIDE];  // [m][k]
    __shared__ unsigned Bs[32 * BSTRIDE];   // [k][n]

    const int tid    = threadIdx.x;
    const int lane   = tid & 31;
    const int wid    = tid >> 5;
    const int warp_m = (wid & 3) * 32;
    const int warp_n = (wid >> 2) * 64;
    const int r      = lane >> 2;  // 0..7
    const int c      = lane & 3;   // 0..3

    const float* Wo = W + (size_t)o * Dd * Ee;

    float acc[2][8][4];
#pragma unroll
    for (int i = 0; i < 2; i++)
#pragma unroll
        for (int j = 0; j < 8; j++)
#pragma unroll
            for (int q = 0; q < 4; q++) acc[i][j][q] = 0.f;

    float4 aST[4], bST[4];

    // prologue: load k-tile 0
#pragma unroll
    for (int i = 0; i < 4; i++) {
        int f = tid + i * 256;
        aST[i] = *reinterpret_cast<const float4*>(&U[(size_t)(row0 + (f >> 3)) * Dd + (f & 7) * 4]);
        bST[i] = *reinterpret_cast<const float4*>(&Wo[(size_t)(f >> 5) * Ee + (f & 31) * 4]);
    }

    for (int t = 0; t < 32; t++) {
        // store staged regs -> smem (with fp32->tf32 round)
#pragma unroll
        for (int i = 0; i < 4; i++) {
            int f = tid + i * 256;
            uint4 ua = make_uint4(f2tf32(aST[i].x), f2tf32(aST[i].y), f2tf32(aST[i].z), f2tf32(aST[i].w));
            *reinterpret_cast<uint4*>(&As[(f >> 3) * ASTRIDE + (f & 7) * 4]) = ua;
            uint4 ub = make_uint4(f2tf32(bST[i].x), f2tf32(bST[i].y), f2tf32(bST[i].z), f2tf32(bST[i].w));
            *reinterpret_cast<uint4*>(&Bs[(f >> 5) * BSTRIDE + (f & 31) * 4]) = ub;
        }
        __syncthreads();

        // prefetch next k-tile while computing
        if (t < 31) {
            int k0 = (t + 1) * 32;
#pragma unroll
            for (int i = 0; i < 4; i++) {
                int f = tid + i * 256;
                aST[i] = *reinterpret_cast<const float4*>(&U[(size_t)(row0 + (f >> 3)) * Dd + k0 + (f & 7) * 4]);
                bST[i] = *reinterpret_cast<const float4*>(&Wo[(size_t)(k0 + (f >> 5)) * Ee + (f & 31) * 4]);
            }
        }

#pragma unroll
        for (int ks = 0; ks < 4; ks++) {
            const int kt = ks * 8;
            unsigned a[2][4];
#pragma unroll
            for (int i = 0; i < 2; i++) {
                int mb = warp_m + i * 16;
                a[i][0] = As[(mb + r) * ASTRIDE + kt + c];
                a[i][1] = As[(mb + r + 8) * ASTRIDE + kt + c];
                a[i][2] = As[(mb + r) * ASTRIDE + kt + c + 4];
                a[i][3] = As[(mb + r + 8) * ASTRIDE + kt + c + 4];
            }
#pragma unroll
            for (int j = 0; j < 8; j++) {
                int nb = warp_n + j * 8;
                unsigned b0 = Bs[(kt + c) * BSTRIDE + nb + r];
                unsigned b1 = Bs[(kt + c + 4) * BSTRIDE + nb + r];
                mma_tf32(acc[0][j], a[0], b0, b1);
                mma_tf32(acc[1][j], a[1], b0, b1);
            }
        }
        __syncthreads();
    }

    // epilogue: write C
    float* outp = g_priors + ((size_t)o * (Bb * Kk) + row0) * Ee;
#pragma unroll
    for (int i = 0; i < 2; i++) {
#pragma unroll
        for (int j = 0; j < 8; j++) {
            int m = warp_m + i * 16 + r;
            int n = warp_n + j * 8 + 2 * c;
            *reinterpret_cast<float2*>(&outp[(size_t)m * Ee + n])       = make_float2(acc[i][j][0], acc[i][j][1]);
            *reinterpret_cast<float2*>(&outp[(size_t)(m + 8) * Ee + n]) = make_float2(acc[i][j][2], acc[i][j][3]);
        }
    }
}

// ---------------------------------------------------------------------------
// Kernel 2a: partial s[b,o,e] over a K/8 slice. grid (48, 8), 128 threads.
// ---------------------------------------------------------------------------
__global__ void __launch_bounds__(128) s_partial(int uniform) {
    const int bo = blockIdx.x;  // b*Oo + o
    const int sl = blockIdx.y;  // 0..7
    const int b  = bo / Oo;
    const int o  = bo % Oo;
    const int e  = threadIdx.x;

    const float* P = g_priors + ((size_t)(o * Bb + b) * Kk + sl * 128) * Ee;

    float s = 0.f;
    if (uniform) {
#pragma unroll 8
        for (int k = 0; k < 128; k++) s += P[(size_t)k * Ee + e];
        s *= (1.f / 6.f);
    } else {
        const float* pr = g_probs + ((size_t)b * Kk + sl * 128) * Oo + o;
#pragma unroll 8
        for (int k = 0; k < 128; k++) s += pr[(size_t)k * Oo] * P[(size_t)k * Ee + e];
    }
    g_spart[(sl * 48 + bo) * Ee + e] = s;
}

// ---------------------------------------------------------------------------
// Kernel 2b: reduce partials + squash. 48 blocks x 128 threads.
// ---------------------------------------------------------------------------
__global__ void __launch_bounds__(128) squash_final() {
    const int bo = blockIdx.x;
    const int e  = threadIdx.x;

    float s = 0.f;
#pragma unroll
    for (int sl = 0; sl < 8; sl++) s += g_spart[(sl * 48 + bo) * Ee + e];

    float x2 = s * s;
#pragma unroll
    for (int off = 16; off > 0; off >>= 1)
        x2 += __shfl_down_sync(0xffffffffu, x2, off);

    __shared__ float ws[4];
    if ((e & 31) == 0) ws[e >> 5] = x2;
    __syncthreads();
    float sq   = ws[0] + ws[1] + ws[2] + ws[3];
    float coef = sq / ((1.f + sq) * (sqrtf(sq) + EPSf));
    g_v[(size_t)bo * Ee + e] = s * coef;
}

// ---------------------------------------------------------------------------
// Kernel 3: logits[b,k,o] (+)= sum_e priors[o,b,k,e]*v[b,o,e]; probs = softmax_o
// (masked -> uniform 1/6). One block per (b,k): 8192 blocks, 6 warps (one per o).
// mask is int32 (numpy bool promoted by the harness).
// ---------------------------------------------------------------------------
__global__ void __launch_bounds__(192) logits_probs(const int* __restrict__ mask,
                                                    int first) {
    const int bkidx = blockIdx.x;       // b*K + k
    const int b     = bkidx >> 10;
    const int o     = threadIdx.x >> 5; // warp id = o
    const int lane  = threadIdx.x & 31;

    const float* P = g_priors + ((size_t)(o * Bb + b) * Kk + (bkidx & (Kk - 1))) * Ee;
    const float* v = g_v + (size_t)(b * Oo + o) * Ee;

    float d = 0.f;
#pragma unroll
    for (int j = 0; j < 4; j++) {
        int e = lane + 32 * j;
        d += P[e] * v[e];
    }
#pragma unroll
    for (int off = 16; off > 0; off >>= 1)
        d += __shfl_down_sync(0xffffffffu, d, off);

    __shared__ float lg[Oo];
    if (lane == 0) {
        float lgv = first ? d : (g_logits[(size_t)bkidx * Oo + o] + d);
        g_logits[(size_t)bkidx * Oo + o] = lgv;
        lg[o] = lgv;
    }
    __syncthreads();

    if (threadIdx.x == 0) {
        float pr[Oo];
        if (mask[bkidx] != 0) {
#pragma unroll
            for (int i = 0; i < Oo; i++) pr[i] = 1.f / 6.f;
        } else {
            float mx = lg[0];
#pragma unroll
            for (int i = 1; i < Oo; i++) mx = fmaxf(mx, lg[i]);
            float sum = 0.f;
#pragma unroll
            for (int i = 0; i < Oo; i++) { pr[i] = expf(lg[i] - mx); sum += pr[i]; }
            float inv = 1.f / sum;
#pragma unroll
            for (int i = 0; i < Oo; i++) pr[i] *= inv;
        }
#pragma unroll
        for (int i = 0; i < Oo; i++) g_probs[(size_t)bkidx * Oo + i] = pr[i];
    }
}

// ---------------------------------------------------------------------------
// Kernel 4: broadcast v[b,o,e] -> out_v[b,l,o,e]  (float4, 25 MB writes)
// ---------------------------------------------------------------------------
__global__ void bcast_v(float4* __restrict__ out) {
    const int total4 = Bb * Ll * Oo * Ee / 4;  // 1,572,864
    int idx = blockIdx.x * blockDim.x + threadIdx.x;
    if (idx >= total4) return;
    int e4 = idx & 31;            // Ee/4 = 32
    int o  = (idx >> 5) % Oo;
    int bl = idx / (32 * Oo);
    int b  = bl >> 10;            // L = 1024
    out[idx] = *reinterpret_cast<const float4*>(&g_v[(size_t)(b * Oo + o) * Ee + e4 * 4]);
}

// ---------------------------------------------------------------------------
// Kernel 5: broadcast probs[b,k,o] -> out_p[b,l,k,o]  (201 MB writes)
// One block per (b,l), copies the 6144-float (b,·) slice.
// ---------------------------------------------------------------------------
__global__ void __launch_bounds__(256) bcast_probs(float* __restrict__ out) {
    const int bl = blockIdx.x;  // b*L + l
    const int b  = bl >> 10;
    const float4* src = reinterpret_cast<const float4*>(g_probs + (size_t)b * (Kk * Oo));
    float4* dst       = reinterpret_cast<float4*>(out + (size_t)bl * (Kk * Oo));
#pragma unroll
    for (int i = threadIdx.x; i < (Kk * Oo / 4); i += 256)
        dst[i] = src[i];
}

// ---------------------------------------------------------------------------
extern "C" void kernel_launch(void* const* d_in, const int* in_sizes, int n_in,
                              void* d_out, int out_size) {
    const float* U = (const float*)d_in[0];               // inputs_u (B,K,D)
    // d_in[1] = context_sequence : provably unused by the reference math
    const float* W = (const float*)d_in[2];               // route_weights (O,D,E)
    const int* mask = (const int*)d_in[3];                // inputs_mask (B,K), bool->int32

    float* out_v = (float*)d_out;                                   // (B,L,O,E)
    float* out_p = (float*)d_out + (size_t)Bb * Ll * Oo * Ee;       // (B,L,K,O)

    // 1. priors = einsum('bkd,ode->bkoe') stored as [o][b][k][e]  (tf32 MMA)
    gemm_priors<<<dim3((Bb * Kk) / 128, Oo), 256>>>(U, W);

    // 2. Routing iterations (L-independent)
    s_partial<<<dim3(48, 8), 128>>>(1);
    squash_final<<<48, 128>>>();              // v0
    logits_probs<<<Bb * Kk, 192>>>(mask, 1);  // logits1, probs1
    s_partial<<<dim3(48, 8), 128>>>(0);
    squash_final<<<48, 128>>>();              // v1
    logits_probs<<<Bb * Kk, 192>>>(mask, 0);  // logits2, probs2
    s_partial<<<dim3(48, 8), 128>>>(0);
    squash_final<<<48, 128>>>();              // v2 (final)

    // 3. Broadcast over L to outputs
    bcast_v<<<(Bb * Ll * Oo * Ee / 4 + 255) / 256, 256>>>((float4*)out_v);
    bcast_probs<<<Bb * Ll, 256>>>(out_p);
}

// round 5
// speedup vs baseline: 2.3573x; 1.1286x over previous
#include <cuda_runtime.h>

// Problem dims
#define Bb 8
#define Kk 1024
#define Ll 1024
#define Dd 1024
#define Oo 6
#define Ee 128
#define EPSf 1e-8f

// Scratch (device globals: allocation-free)
__device__ float g_priors[(size_t)Oo * Bb * Kk * Ee];  // [o][b][k][e]  (25 MB)
__device__ float g_v[Bb * Oo * Ee];                    // squashed v per (b,o)
__device__ float g_logits[Bb * Kk * Oo];
__device__ float g_probs[Bb * Kk * Oo];                // [b][k][o]
__device__ float g_spart[16 * 48 * Ee];                // k-sliced partial sums

__device__ __forceinline__ unsigned f2tf32(float f) {
    unsigned r;
    asm("cvt.rna.tf32.f32 %0, %1;" : "=r"(r) : "f"(f));
    return r;
}

__device__ __forceinline__ void mma_tf32(float* c, const unsigned* a, unsigned b0, unsigned b1) {
    asm volatile(
        "mma.sync.aligned.m16n8k8.row.col.f32.tf32.tf32.f32 "
        "{%0,%1,%2,%3}, {%4,%5,%6,%7}, {%8,%9}, {%0,%1,%2,%3};\n"
        : "+f"(c[0]), "+f"(c[1]), "+f"(c[2]), "+f"(c[3])
        : "r"(a[0]), "r"(a[1]), "r"(a[2]), "r"(a[3]), "r"(b0), "r"(b1));
}

// ---------------------------------------------------------------------------
// Kernel 1: priors GEMM via tf32 mma, double-buffered smem, fused iter-0
// k-partial-sum epilogue (probs uniform 1/6 at iteration 0).
// For each o: C[8192 x 128] = U[8192 x 1024] * W_o[1024 x 128]
// Block tile 128x128xK32, 256 threads = 8 warps (4 m x 2 n), warp tile 32x64.
// ---------------------------------------------------------------------------
#define ASTRIDE 36   // 32 + 4 pad
#define BSTRIDE 136  // 128 + 8 pad

__global__ void __launch_bounds__(256) gemm_priors(const float* __restrict__ U,
                                                   const float* __restrict__ W) {
    const int o    = blockIdx.y;
    const int row0 = blockIdx.x * 128;
    const int b    = blockIdx.x >> 3;   // 8 tiles per b
    const int tile = blockIdx.x & 7;

    __shared__ unsigned As[2][128 * ASTRIDE];
    __shared__ unsigned Bs[2][32 * BSTRIDE];

    const int tid    = threadIdx.x;
    const int lane   = tid & 31;
    const int wid    = tid >> 5;
    const int warp_m = (wid & 3) * 32;
    const int warp_n = (wid >> 2) * 64;
    const int r      = lane >> 2;  // 0..7
    const int c      = lane & 3;   // 0..3

    const float* Wo = W + (size_t)o * Dd * Ee;

    float acc[2][8][4];
#pragma unroll
    for (int i = 0; i < 2; i++)
#pragma unroll
        for (int j = 0; j < 8; j++)
#pragma unroll
            for (int q = 0; q < 4; q++) acc[i][j][q] = 0.f;

    float4 aST[4], bST[4];

    // prologue: load + store k-tile 0 into buffer 0
#pragma unroll
    for (int i = 0; i < 4; i++) {
        int f = tid + i * 256;
        aST[i] = *reinterpret_cast<const float4*>(&U[(size_t)(row0 + (f >> 3)) * Dd + (f & 7) * 4]);
        bST[i] = *reinterpret_cast<const float4*>(&Wo[(size_t)(f >> 5) * Ee + (f & 31) * 4]);
    }
#pragma unroll
    for (int i = 0; i < 4; i++) {
        int f = tid + i * 256;
        *reinterpret_cast<uint4*>(&As[0][(f >> 3) * ASTRIDE + (f & 7) * 4]) =
            make_uint4(f2tf32(aST[i].x), f2tf32(aST[i].y), f2tf32(aST[i].z), f2tf32(aST[i].w));
        *reinterpret_cast<uint4*>(&Bs[0][(f >> 5) * BSTRIDE + (f & 31) * 4]) =
            make_uint4(f2tf32(bST[i].x), f2tf32(bST[i].y), f2tf32(bST[i].z), f2tf32(bST[i].w));
    }
    __syncthreads();

    for (int t = 0; t < 32; t++) {
        const int cur = t & 1;
        // prefetch next k-tile into registers (overlaps with MMA below)
        if (t < 31) {
            int k0 = (t + 1) * 32;
#pragma unroll
            for (int i = 0; i < 4; i++) {
                int f = tid + i * 256;
                aST[i] = *reinterpret_cast<const float4*>(&U[(size_t)(row0 + (f >> 3)) * Dd + k0 + (f & 7) * 4]);
                bST[i] = *reinterpret_cast<const float4*>(&Wo[(size_t)(k0 + (f >> 5)) * Ee + (f & 31) * 4]);
            }
        }

#pragma unroll
        for (int ks = 0; ks < 4; ks++) {
            const int kt = ks * 8;
            unsigned a[2][4];
#pragma unroll
            for (int i = 0; i < 2; i++) {
                int mb = warp_m + i * 16;
                a[i][0] = As[cur][(mb + r) * ASTRIDE + kt + c];
                a[i][1] = As[cur][(mb + r + 8) * ASTRIDE + kt + c];
                a[i][2] = As[cur][(mb + r) * ASTRIDE + kt + c + 4];
                a[i][3] = As[cur][(mb + r + 8) * ASTRIDE + kt + c + 4];
            }
#pragma unroll
            for (int j = 0; j < 8; j++) {
                int nb = warp_n + j * 8;
                unsigned b0 = Bs[cur][(kt + c) * BSTRIDE + nb + r];
                unsigned b1 = Bs[cur][(kt + c + 4) * BSTRIDE + nb + r];
                mma_tf32(acc[0][j], a[0], b0, b1);
                mma_tf32(acc[1][j], a[1], b0, b1);
            }
        }

        if (t < 31) {
            const int nxt = 1 - cur;
#pragma unroll
            for (int i = 0; i < 4; i++) {
                int f = tid + i * 256;
                *reinterpret_cast<uint4*>(&As[nxt][(f >> 3) * ASTRIDE + (f & 7) * 4]) =
                    make_uint4(f2tf32(aST[i].x), f2tf32(aST[i].y), f2tf32(aST[i].z), f2tf32(aST[i].w));
                *reinterpret_cast<uint4*>(&Bs[nxt][(f >> 5) * BSTRIDE + (f & 31) * 4]) =
                    make_uint4(f2tf32(bST[i].x), f2tf32(bST[i].y), f2tf32(bST[i].z), f2tf32(bST[i].w));
            }
            __syncthreads();
        }
    }

    // write C
    float* outp = g_priors + ((size_t)o * (Bb * Kk) + row0) * Ee;
#pragma unroll
    for (int i = 0; i < 2; i++) {
#pragma unroll
        for (int j = 0; j < 8; j++) {
            int m = warp_m + i * 16 + r;
            int n = warp_n + j * 8 + 2 * c;
            *reinterpret_cast<float2*>(&outp[(size_t)m * Ee + n])       = make_float2(acc[i][j][0], acc[i][j][1]);
            *reinterpret_cast<float2*>(&outp[(size_t)(m + 8) * Ee + n]) = make_float2(acc[i][j][2], acc[i][j][3]);
        }
    }

    // ---- fused iter-0 partial sum: sum over this tile's 128 m-rows, split
    // into two 64-row halves -> g_spart slices tile*2 + h (16 slices total).
    __shared__ float sacc2[2][128];
    __syncthreads();
    if (tid < 256) sacc2[tid >> 7][tid & 127] = 0.f;
    __syncthreads();

    const int h = (wid & 3) >> 1;  // warps 0,1 -> rows 0..63 ; warps 2,3 -> 64..127
#pragma unroll
    for (int j = 0; j < 8; j++) {
        float v0 = acc[0][j][0] + acc[0][j][2] + acc[1][j][0] + acc[1][j][2];
        float v1 = acc[0][j][1] + acc[0][j][3] + acc[1][j][1] + acc[1][j][3];
#pragma unroll
        for (int off = 16; off >= 4; off >>= 1) {
            v0 += __shfl_down_sync(0xffffffffu, v0, off);
            v1 += __shfl_down_sync(0xffffffffu, v1, off);
        }
        if (lane < 4) {
            atomicAdd(&sacc2[h][warp_n + j * 8 + 2 * lane], v0);
            atomicAdd(&sacc2[h][warp_n + j * 8 + 2 * lane + 1], v1);
        }
    }
    __syncthreads();
    if (tid < 256) {
        int hh = tid >> 7, e = tid & 127;
        g_spart[((tile * 2 + hh) * 48 + b * Oo + o) * Ee + e] = sacc2[hh][e] * (1.f / 6.f);
    }
}

// ---------------------------------------------------------------------------
// Kernel 2: reduce partials + squash. 48 blocks x 128 threads.
// ---------------------------------------------------------------------------
__global__ void __launch_bounds__(128) squash_final(int nsl) {
    const int bo = blockIdx.x;
    const int e  = threadIdx.x;

    float s = 0.f;
    for (int sl = 0; sl < nsl; sl++) s += g_spart[(sl * 48 + bo) * Ee + e];

    float x2 = s * s;
#pragma unroll
    for (int off = 16; off > 0; off >>= 1)
        x2 += __shfl_down_sync(0xffffffffu, x2, off);

    __shared__ float ws[4];
    if ((e & 31) == 0) ws[e >> 5] = x2;
    __syncthreads();
    float sq   = ws[0] + ws[1] + ws[2] + ws[3];
    float coef = sq / ((1.f + sq) * (sqrtf(sq) + EPSf));
    g_v[(size_t)bo * Ee + e] = s * coef;
}

// ---------------------------------------------------------------------------
// Kernel 3: fused routing iteration. For each (b,k):
//   d_o   = <priors[o,b,k,:], v[b,o,:]>
//   lg_o  = (first ? d_o : logits + d_o)   (stored; skipped when masked)
//   p     = mask ? 1/6 : softmax(lg)       (stored to g_probs)
//   spart += p_o * priors[o,b,k,:]
// grid (8 b, 8 sl) x 512 threads (16 warps, warp handles 8 contiguous k).
// Single pass over priors per iteration (was two).
// ---------------------------------------------------------------------------
__global__ void __launch_bounds__(512) fused_iter(const int* __restrict__ mask, int first) {
    const int b    = blockIdx.x;
    const int sl   = blockIdx.y;
    const int w    = threadIdx.x >> 5;
    const int lane = threadIdx.x & 31;

    // v fragments: e = lane*4 .. lane*4+3
    float4 vv[Oo];
#pragma unroll
    for (int o = 0; o < Oo; o++)
        vv[o] = *reinterpret_cast<const float4*>(&g_v[(size_t)(b * Oo + o) * Ee + lane * 4]);

    float4 sacc[Oo];
#pragma unroll
    for (int o = 0; o < Oo; o++) sacc[o] = make_float4(0.f, 0.f, 0.f, 0.f);

#pragma unroll 1
    for (int t = 0; t < 8; t++) {
        const int k   = sl * 128 + w * 8 + t;
        const int idx = b * Kk + k;

        float4 P4[Oo];
#pragma unroll
        for (int o = 0; o < Oo; o++)
            P4[o] = *reinterpret_cast<const float4*>(
                &g_priors[((size_t)(o * Bb + b) * Kk + k) * Ee + lane * 4]);

        const int m = mask[idx];
        float p[Oo];
        if (m) {
#pragma unroll
            for (int o = 0; o < Oo; o++) p[o] = 1.f / 6.f;
        } else {
            float d[Oo];
#pragma unroll
            for (int o = 0; o < Oo; o++)
                d[o] = P4[o].x * vv[o].x + P4[o].y * vv[o].y + P4[o].z * vv[o].z + P4[o].w * vv[o].w;
#pragma unroll
            for (int off = 16; off > 0; off >>= 1)
#pragma unroll
                for (int o = 0; o < Oo; o++)
                    d[o] += __shfl_xor_sync(0xffffffffu, d[o], off);

            float lg[Oo];
            if (first) {
#pragma unroll
                for (int o = 0; o < Oo; o++) lg[o] = d[o];
            } else {
                float myold = (lane < Oo) ? g_logits[(size_t)idx * Oo + lane] : 0.f;
#pragma unroll
                for (int o = 0; o < Oo; o++)
                    lg[o] = __shfl_sync(0xffffffffu, myold, o) + d[o];
            }
            if (lane < Oo) g_logits[(size_t)idx * Oo + lane] = lg[lane];

            float mx = lg[0];
#pragma unroll
            for (int o = 1; o < Oo; o++) mx = fmaxf(mx, lg[o]);
            float sum = 0.f;
#pragma unroll
            for (int o = 0; o < Oo; o++) { p[o] = __expf(lg[o] - mx); sum += p[o]; }
            float inv = 1.f / sum;
#pragma unroll
            for (int o = 0; o < Oo; o++) p[o] *= inv;
        }

        if (lane < Oo) g_probs[(size_t)idx * Oo + lane] = p[lane];

#pragma unroll
        for (int o = 0; o < Oo; o++) {
            sacc[o].x += p[o] * P4[o].x;
            sacc[o].y += p[o] * P4[o].y;
            sacc[o].z += p[o] * P4[o].z;
            sacc[o].w += p[o] * P4[o].w;
        }
    }

    // block reduction of per-warp partials (16 x 768 floats = 48KB)
    __shared__ float sred[16][Oo * Ee];
#pragma unroll
    for (int o = 0; o < Oo; o++)
        *reinterpret_cast<float4*>(&sred[w][o * Ee + lane * 4]) = sacc[o];
    __syncthreads();

    for (int i = threadIdx.x; i < Oo * Ee; i += 512) {
        float s = 0.f;
#pragma unroll
        for (int ww = 0; ww < 16; ww++) s += sred[ww][i];
        g_spart[(sl * 48 + b * Oo + (i >> 7)) * Ee + (i & 127)] = s;
    }
}

// ---------------------------------------------------------------------------
// Kernel 4: broadcast v[b,o,e] -> out_v[b,l,o,e]  (float4, 25 MB writes)
// ---------------------------------------------------------------------------
__global__ void bcast_v(float4* __restrict__ out) {
    const int total4 = Bb * Ll * Oo * Ee / 4;  // 1,572,864
    int idx = blockIdx.x * blockDim.x + threadIdx.x;
    if (idx >= total4) return;
    int e4 = idx & 31;            // Ee/4 = 32
    int o  = (idx >> 5) % Oo;
    int bl = idx / (32 * Oo);
    int b  = bl >> 10;            // L = 1024
    out[idx] = *reinterpret_cast<const float4*>(&g_v[(size_t)(b * Oo + o) * Ee + e4 * 4]);
}

// ---------------------------------------------------------------------------
// Kernel 5: broadcast probs[b,k,o] -> out_p[b,l,k,o]  (201 MB writes)
// ---------------------------------------------------------------------------
__global__ void __launch_bounds__(256) bcast_probs(float* __restrict__ out) {
    const int bl = blockIdx.x;  // b*L + l
    const int b  = bl >> 10;
    const float4* src = reinterpret_cast<const float4*>(g_probs + (size_t)b * (Kk * Oo));
    float4* dst       = reinterpret_cast<float4*>(out + (size_t)bl * (Kk * Oo));
#pragma unroll
    for (int i = threadIdx.x; i < (Kk * Oo / 4); i += 256)
        dst[i] = src[i];
}

// ---------------------------------------------------------------------------
extern "C" void kernel_launch(void* const* d_in, const int* in_sizes, int n_in,
                              void* d_out, int out_size) {
    const float* U = (const float*)d_in[0];               // inputs_u (B,K,D)
    // d_in[1] = context_sequence : provably unused by the reference math
    const float* W = (const float*)d_in[2];               // route_weights (O,D,E)
    const int* mask = (const int*)d_in[3];                // inputs_mask (B,K), bool->int32

    float* out_v = (float*)d_out;                                   // (B,L,O,E)
    float* out_p = (float*)d_out + (size_t)Bb * Ll * Oo * Ee;       // (B,L,K,O)

    // 1. priors GEMM (tf32 MMA) + fused iter-0 k-partials (16 slices)
    gemm_priors<<<dim3((Bb * Kk) / 128, Oo), 256>>>(U, W);
    squash_final<<<48, 128>>>(16);            // v0

    // 2. Routing iterations (L-independent), one priors pass per iteration
    fused_iter<<<dim3(Bb, 8), 512>>>(mask, 1);  // logits1, probs1, spart
    squash_final<<<48, 128>>>(8);             // v1
    fused_iter<<<dim3(Bb, 8), 512>>>(mask, 0);  // logits2, probs2, spart
    squash_final<<<48, 128>>>(8);             // v2 (final)

    // 3. Broadcast over L to outputs
    bcast_v<<<(Bb * Ll * Oo * Ee / 4 + 255) / 256, 256>>>((float4*)out_v);
    bcast_probs<<<Bb * Ll, 256>>>(out_p);
}